// round 14
// baseline (speedup 1.0000x reference)
#include <cuda_runtime.h>
#include <math.h>

#define BD 8
#define HD 48
#define WD 48
#define CD 256
#define NPIX (BD * HD * WD)     // 18432
#define PIXB (HD * WD)          // 2304 pixels per batch
#define PLANE (HD * WD)         // 2304 elems per corr plane
#define PPB   16                // pixels per k_stats block (8 warps x 2)
#define NBLK1 (NPIX / PPB)      // 1152
#define BLKPB (PIXB / PPB)      // 144 stats blocks per batch

// ---- scratch (device globals; no allocation allowed) ----
__device__ float    g_cvraw[NPIX * 2];
__device__ float    g_partials[NBLK1 * 2];   // (sum, sumsq) per block
__device__ float    g_stats[BD * 2];         // (mu, inv_std) per batch
__device__ unsigned g_tick[BD];              // ticket counters (self-resetting)

// ================= Kernel 1: MLP + mean + cvraw + fused per-batch reduction =========
// R8 body (17KB smem, x in registers, multi-value butterfly — 15.0us measured)
// + last-block-per-batch deterministic reduction + PDL trigger at the end.
__global__ __launch_bounds__(256) void k_stats(
    const float* __restrict__ x,
    const float* __restrict__ map_w, const float* __restrict__ map_b,
    const float* __restrict__ mean_w, const float* __restrict__ mean_b,
    const float* __restrict__ cov_w, const float* __restrict__ cov_b,
    float* __restrict__ out_mean)
{
    __shared__ float4 sw4[16 * 64];   // map_w as float4 [o][c/4], 16KB
    __shared__ float red[PPB * 2];    // per-pixel (sum, sumsq)
    __shared__ float sred[BLKPB], sqred[BLKPB];
    __shared__ int   s_last;
    const int tid = threadIdx.x;
    {
        const float4* w4 = (const float4*)map_w;
        for (int i = tid; i < 16 * 64; i += 256) sw4[i] = w4[i];
    }
    __syncthreads();

    const int warp = tid >> 5, lane = tid & 31;
    const int batch = blockIdx.x / BLKPB;
    const int pidA = blockIdx.x * PPB + warp * 2;   // pixel A (B = A+1)

    const float4* __restrict__ x4 = (const float4*)x;
    const float4 xA0 = x4[(size_t)pidA * 64 + lane];
    const float4 xA1 = x4[(size_t)pidA * 64 + 32 + lane];
    const float4 xB0 = x4[(size_t)(pidA + 1) * 64 + lane];
    const float4 xB1 = x4[(size_t)(pidA + 1) * 64 + 32 + lane];

    float acc[32];
#pragma unroll
    for (int o = 0; o < 16; o++) {
        const float4 w0 = sw4[o * 64 + lane];
        const float4 w1 = sw4[o * 64 + 32 + lane];
        float a = xA0.x * w0.x;
        a = fmaf(xA0.y, w0.y, a); a = fmaf(xA0.z, w0.z, a); a = fmaf(xA0.w, w0.w, a);
        a = fmaf(xA1.x, w1.x, a); a = fmaf(xA1.y, w1.y, a);
        a = fmaf(xA1.z, w1.z, a); a = fmaf(xA1.w, w1.w, a);
        float c = xB0.x * w0.x;
        c = fmaf(xB0.y, w0.y, c); c = fmaf(xB0.z, w0.z, c); c = fmaf(xB0.w, w0.w, c);
        c = fmaf(xB1.x, w1.x, c); c = fmaf(xB1.y, w1.y, c);
        c = fmaf(xB1.z, w1.z, c); c = fmaf(xB1.w, w1.w, c);
        acc[o] = a;
        acc[16 + o] = c;
    }

    // Multi-value butterfly: lane l ends holding the full sum of acc[l]
#pragma unroll
    for (int d = 16; d >= 1; d >>= 1) {
        const int half = d;
#pragma unroll
        for (int j = 0; j < 16; j++) {
            if (j < half) {
                float send = (lane & d) ? acc[j] : acc[j + half];
                float recv = __shfl_xor_sync(0xffffffffu, send, d);
                float mine = (lane & d) ? acc[j + half] : acc[j];
                acc[j] = mine + recv;
            }
        }
    }
    const int o = lane & 15;
    const float tt = tanhf(acc[0] + __ldg(&map_b[o]));

    float vals[4];
    vals[0] = tt * __ldg(&mean_w[o]);
    vals[1] = tt * __ldg(&mean_w[16 + o]);
    vals[2] = tt * __ldg(&cov_w[o]);
    vals[3] = tt * __ldg(&cov_w[16 + o]);
    {   // d=8: 4->2
        float send = (lane & 8) ? vals[0] : vals[2];
        float recv = __shfl_xor_sync(0xffffffffu, send, 8);
        vals[0] = ((lane & 8) ? vals[2] : vals[0]) + recv;
        send = (lane & 8) ? vals[1] : vals[3];
        recv = __shfl_xor_sync(0xffffffffu, send, 8);
        vals[1] = ((lane & 8) ? vals[3] : vals[1]) + recv;
    }
    {   // d=4: 2->1
        float send = (lane & 4) ? vals[0] : vals[1];
        float recv = __shfl_xor_sync(0xffffffffu, send, 4);
        vals[0] = ((lane & 4) ? vals[1] : vals[0]) + recv;
    }
    vals[0] += __shfl_xor_sync(0xffffffffu, vals[0], 2);
    vals[0] += __shfl_xor_sync(0xffffffffu, vals[0], 1);
    // quad q = (lane&15)>>2: q0=m0, q1=m1, q2=c0, q3=c1 (replicated x4)

    const int p = lane >> 4;
    const int pid = pidA + p;
    const int hl = lane & 15;
    const int q = hl >> 2;
    const int hw = pid % PIXB;
    const float r = vals[0];

    if (hl == 0) out_mean[pid * 2 + 0] = (float)(hw % WD) + __ldg(&mean_b[0]) + r;
    if (hl == 4) out_mean[pid * 2 + 1] = (float)(hw / WD) + __ldg(&mean_b[1]) + r;

    const float cb = r + __ldg(&cov_b[q & 1]);
    const float ex = __shfl_xor_sync(0xffffffffu, cb, 4);
    if (hl == 8)  g_cvraw[pid * 2 + 0] = cb;
    if (hl == 12) g_cvraw[pid * 2 + 1] = cb;
    if (hl == 8) {
        red[(warp * 2 + p) * 2 + 0] = cb + ex;
        red[(warp * 2 + p) * 2 + 1] = cb * cb + ex * ex;
    }
    __syncthreads();

    // block partial (fixed order) + ticket
    if (tid == 0) {
        float s = 0.f, qq = 0.f;
#pragma unroll
        for (int i = 0; i < PPB; i++) { s += red[i * 2]; qq += red[i * 2 + 1]; }
        g_partials[blockIdx.x * 2 + 0] = s;
        g_partials[blockIdx.x * 2 + 1] = qq;
        __threadfence();
        const unsigned prev = atomicAdd(&g_tick[batch], 1u);
        s_last = (prev == BLKPB - 1);
    }
    __syncthreads();

    // elected last block of this batch: deterministic fixed-order reduction
    if (s_last) {
        __threadfence();
        if (tid < BLKPB) {
            sred[tid]  = g_partials[(batch * BLKPB + tid) * 2 + 0];
            sqred[tid] = g_partials[(batch * BLKPB + tid) * 2 + 1];
        }
        __syncthreads();
        if (tid == 0) {
            float s = 0.f, qq = 0.f;
#pragma unroll
            for (int i = 0; i < BLKPB; i++) { s += sred[i]; qq += sqred[i]; }
            const float n = (float)(PIXB * 2);     // 4608
            const float mu = s / n;
            const float var = qq / n - mu * mu + 1e-5f;
            g_stats[batch * 2 + 0] = mu;
            g_stats[batch * 2 + 1] = rsqrtf(var);
            g_tick[batch] = 0;                     // reset for next graph replay
        }
        __syncthreads();                           // g_stats written before trigger
    }

    // PDL: allow the dependent k_apply grid to proceed. Fires once ALL CTAs
    // have triggered or exited — the elected block triggers only after g_stats.
    asm volatile("griddepcontrol.launch_dependents;" ::: "memory");
}

// ================= Kernel 2: HBM-bound apply (PDL consumer) =================
// Scheduled while k_stats still runs: issues its 3 stats-independent streaming
// loads first, then griddepcontrol.wait gates the param reads.
__global__ __launch_bounds__(192) void k_apply(
    const float* __restrict__ corr, float* __restrict__ out,
    const float* __restrict__ mean_arr, float* __restrict__ out_det)
{
    const int pid = blockIdx.x;
    const int t = threadIdx.x;
    const float4* __restrict__ src = (const float4*)(corr + (size_t)pid * PLANE);
    float4* __restrict__ dst = (float4*)(out + (size_t)pid * PLANE);

    // stats-independent DRAM loads — overlap with the producer grid
    float4 c[3];
#pragma unroll
    for (int it = 0; it < 3; it++) c[it] = __ldcs(src + t + it * 192);

    // wait for k_stats grid (g_stats/g_cvraw/out_mean visible afterwards)
    asm volatile("griddepcontrol.wait;" ::: "memory");

    const int b = pid / PIXB;
    const float mu = g_stats[b * 2 + 0], istd = g_stats[b * 2 + 1];
    float c0 = (g_cvraw[pid * 2 + 0] - mu) * istd;
    float c1 = (g_cvraw[pid * 2 + 1] - mu) * istd;
    c0 = 5.f / (1.f + __expf(-c0)) + 0.05f;
    c1 = 5.f / (1.f + __expf(-c1)) + 0.05f;
    const float det = c0 * c1;
    if (t == 0) out_det[pid] = det;
    const float mx = __ldg(&mean_arr[pid * 2 + 0]);
    const float my = __ldg(&mean_arr[pid * 2 + 1]);
    const float ax = -0.5f / c0;
    const float ay = -0.5f / c1;
    const float s = rsqrtf(det) * (1.0f / 6.28f);

#pragma unroll
    for (int it = 0; it < 3; it++) {
        const int i = t + it * 192;          // float4 index in plane (0..575)
        const int h2 = i / 12;               // 12 float4s per 48-float row
        const float dy = (float)h2 - my;
        const bool iny = fabsf(dy) <= 6.0f;
        const float qy = ay * dy * dy;
        const float dx0 = (float)((i % 12) * 4) - mx;
        float4 v = c[it];
        {
            const float dx = dx0 + 0.f;
            if (iny && fabsf(dx) <= 6.0f)
                v.x = fmaf(v.x * s, __expf(fmaf(ax, dx * dx, qy)), v.x);
        }
        {
            const float dx = dx0 + 1.f;
            if (iny && fabsf(dx) <= 6.0f)
                v.y = fmaf(v.y * s, __expf(fmaf(ax, dx * dx, qy)), v.y);
        }
        {
            const float dx = dx0 + 2.f;
            if (iny && fabsf(dx) <= 6.0f)
                v.z = fmaf(v.z * s, __expf(fmaf(ax, dx * dx, qy)), v.z);
        }
        {
            const float dx = dx0 + 3.f;
            if (iny && fabsf(dx) <= 6.0f)
                v.w = fmaf(v.w * s, __expf(fmaf(ax, dx * dx, qy)), v.w);
        }
        __stcs(dst + i, v);
    }
}

// ======================================================================
extern "C" void kernel_launch(void* const* d_in, const int* in_sizes, int n_in,
                              void* d_out, int out_size)
{
    const float* x      = (const float*)d_in[0];
    const float* corr   = (const float*)d_in[1];
    const float* map_w  = (const float*)d_in[2];
    const float* map_b  = (const float*)d_in[3];
    const float* mean_w = (const float*)d_in[4];
    const float* mean_b = (const float*)d_in[5];
    const float* cov_w  = (const float*)d_in[6];
    const float* cov_b  = (const float*)d_in[7];

    float* out = (float*)d_out;
    // outputs concatenated flat: corr1 (b,h,w,h,w), mean (b,h,w,2), det (b,h*w)
    float* out_corr1 = out;
    float* out_mean  = out + (size_t)NPIX * PLANE;
    float* out_det   = out_mean + (size_t)NPIX * 2;

    k_stats<<<NBLK1, 256>>>(x, map_w, map_b, mean_w, mean_b, cov_w, cov_b, out_mean);

    // k_apply with programmatic dependent launch: overlaps its scheduling and
    // stats-independent DRAM loads with k_stats execution.
    cudaLaunchConfig_t cfg = {};
    cfg.gridDim = dim3(NPIX);
    cfg.blockDim = dim3(192);
    cfg.dynamicSmemBytes = 0;
    cfg.stream = 0;
    cudaLaunchAttribute attrs[1];
    attrs[0].id = cudaLaunchAttributeProgrammaticStreamSerialization;
    attrs[0].val.programmaticStreamSerializationAllowed = 1;
    cfg.attrs = attrs;
    cfg.numAttrs = 1;
    cudaLaunchKernelEx(&cfg, k_apply, corr, out_corr1,
                       (const float*)out_mean, out_det);
}

// round 15
// speedup vs baseline: 1.1224x; 1.1224x over previous
#include <cuda_runtime.h>
#include <math.h>

#define BD 8
#define HD 48
#define WD 48
#define CD 256
#define NPIX (BD * HD * WD)     // 18432
#define PIXB (HD * WD)          // 2304 pixels per batch
#define PLANE (HD * WD)         // 2304 elems per corr plane
#define PPB   16                // pixels per k_stats block (8 warps x 2)
#define NBLK1 (NPIX / PPB)      // 1152
#define BLKPB (PIXB / PPB)      // 144 stats blocks per batch

// ---- scratch (device globals; no allocation allowed) ----
__device__ float    g_cvraw[NPIX * 2];
__device__ float    g_partials[NBLK1 * 2];   // (sum, sumsq) per block
__device__ float    g_stats[BD * 2];         // (mu, inv_std) per batch
__device__ unsigned g_tick[BD];              // ticket counters (self-resetting)

// ================= Kernel 1: MLP + mean + cvraw + fused per-batch reduction =========
// R8 body (measured 15.0us) + last-block ticket reduction (R12, deterministic).
__global__ __launch_bounds__(256) void k_stats(
    const float* __restrict__ x,
    const float* __restrict__ map_w, const float* __restrict__ map_b,
    const float* __restrict__ mean_w, const float* __restrict__ mean_b,
    const float* __restrict__ cov_w, const float* __restrict__ cov_b,
    float* __restrict__ out_mean)
{
    __shared__ float4 sw4[16 * 64];   // map_w as float4 [o][c/4], 16KB
    __shared__ float red[PPB * 2];    // per-pixel (sum, sumsq)
    __shared__ float sred[BLKPB], sqred[BLKPB];
    __shared__ int   s_last;
    const int tid = threadIdx.x;
    {
        const float4* w4 = (const float4*)map_w;
        for (int i = tid; i < 16 * 64; i += 256) sw4[i] = w4[i];
    }
    __syncthreads();

    const int warp = tid >> 5, lane = tid & 31;
    const int batch = blockIdx.x / BLKPB;
    const int pidA = blockIdx.x * PPB + warp * 2;   // pixel A (B = A+1)

    const float4* __restrict__ x4 = (const float4*)x;
    const float4 xA0 = x4[(size_t)pidA * 64 + lane];
    const float4 xA1 = x4[(size_t)pidA * 64 + 32 + lane];
    const float4 xB0 = x4[(size_t)(pidA + 1) * 64 + lane];
    const float4 xB1 = x4[(size_t)(pidA + 1) * 64 + 32 + lane];

    float acc[32];
#pragma unroll
    for (int o = 0; o < 16; o++) {
        const float4 w0 = sw4[o * 64 + lane];
        const float4 w1 = sw4[o * 64 + 32 + lane];
        float a = xA0.x * w0.x;
        a = fmaf(xA0.y, w0.y, a); a = fmaf(xA0.z, w0.z, a); a = fmaf(xA0.w, w0.w, a);
        a = fmaf(xA1.x, w1.x, a); a = fmaf(xA1.y, w1.y, a);
        a = fmaf(xA1.z, w1.z, a); a = fmaf(xA1.w, w1.w, a);
        float c = xB0.x * w0.x;
        c = fmaf(xB0.y, w0.y, c); c = fmaf(xB0.z, w0.z, c); c = fmaf(xB0.w, w0.w, c);
        c = fmaf(xB1.x, w1.x, c); c = fmaf(xB1.y, w1.y, c);
        c = fmaf(xB1.z, w1.z, c); c = fmaf(xB1.w, w1.w, c);
        acc[o] = a;
        acc[16 + o] = c;
    }

    // Multi-value butterfly: lane l ends holding the full sum of acc[l]
#pragma unroll
    for (int d = 16; d >= 1; d >>= 1) {
        const int half = d;
#pragma unroll
        for (int j = 0; j < 16; j++) {
            if (j < half) {
                float send = (lane & d) ? acc[j] : acc[j + half];
                float recv = __shfl_xor_sync(0xffffffffu, send, d);
                float mine = (lane & d) ? acc[j + half] : acc[j];
                acc[j] = mine + recv;
            }
        }
    }
    const int o = lane & 15;
    const float tt = tanhf(acc[0] + __ldg(&map_b[o]));

    float vals[4];
    vals[0] = tt * __ldg(&mean_w[o]);
    vals[1] = tt * __ldg(&mean_w[16 + o]);
    vals[2] = tt * __ldg(&cov_w[o]);
    vals[3] = tt * __ldg(&cov_w[16 + o]);
    {   // d=8: 4->2
        float send = (lane & 8) ? vals[0] : vals[2];
        float recv = __shfl_xor_sync(0xffffffffu, send, 8);
        vals[0] = ((lane & 8) ? vals[2] : vals[0]) + recv;
        send = (lane & 8) ? vals[1] : vals[3];
        recv = __shfl_xor_sync(0xffffffffu, send, 8);
        vals[1] = ((lane & 8) ? vals[3] : vals[1]) + recv;
    }
    {   // d=4: 2->1
        float send = (lane & 4) ? vals[0] : vals[1];
        float recv = __shfl_xor_sync(0xffffffffu, send, 4);
        vals[0] = ((lane & 4) ? vals[1] : vals[0]) + recv;
    }
    vals[0] += __shfl_xor_sync(0xffffffffu, vals[0], 2);
    vals[0] += __shfl_xor_sync(0xffffffffu, vals[0], 1);
    // quad q = (lane&15)>>2: q0=m0, q1=m1, q2=c0, q3=c1 (replicated x4)

    const int p = lane >> 4;
    const int pid = pidA + p;
    const int hl = lane & 15;
    const int q = hl >> 2;
    const int hw = pid % PIXB;
    const float r = vals[0];

    if (hl == 0) out_mean[pid * 2 + 0] = (float)(hw % WD) + __ldg(&mean_b[0]) + r;
    if (hl == 4) out_mean[pid * 2 + 1] = (float)(hw / WD) + __ldg(&mean_b[1]) + r;

    const float cb = r + __ldg(&cov_b[q & 1]);
    const float ex = __shfl_xor_sync(0xffffffffu, cb, 4);
    if (hl == 8)  g_cvraw[pid * 2 + 0] = cb;
    if (hl == 12) g_cvraw[pid * 2 + 1] = cb;
    if (hl == 8) {
        red[(warp * 2 + p) * 2 + 0] = cb + ex;
        red[(warp * 2 + p) * 2 + 1] = cb * cb + ex * ex;
    }
    __syncthreads();

    // block partial (fixed order) + ticket
    if (tid == 0) {
        float s = 0.f, qq = 0.f;
#pragma unroll
        for (int i = 0; i < PPB; i++) { s += red[i * 2]; qq += red[i * 2 + 1]; }
        g_partials[blockIdx.x * 2 + 0] = s;
        g_partials[blockIdx.x * 2 + 1] = qq;
        __threadfence();
        const unsigned prev = atomicAdd(&g_tick[batch], 1u);
        s_last = (prev == BLKPB - 1);
    }
    __syncthreads();

    // elected last block of this batch: deterministic fixed-order reduction
    if (s_last) {
        __threadfence();
        if (tid < BLKPB) {
            sred[tid]  = g_partials[(batch * BLKPB + tid) * 2 + 0];
            sqred[tid] = g_partials[(batch * BLKPB + tid) * 2 + 1];
        }
        __syncthreads();
        if (tid == 0) {
            float s = 0.f, qq = 0.f;
#pragma unroll
            for (int i = 0; i < BLKPB; i++) { s += sred[i]; qq += sqred[i]; }
            const float n = (float)(PIXB * 2);     // 4608
            const float mu = s / n;
            const float var = qq / n - mu * mu + 1e-5f;
            g_stats[batch * 2 + 0] = mu;
            g_stats[batch * 2 + 1] = rsqrtf(var);
            g_tick[batch] = 0;                     // reset for next graph replay
        }
    }
}

// ================= Kernel 2: HBM-bound apply (best measured: 47.1us, 76.5% DRAM) ===
__global__ __launch_bounds__(192) void k_apply(
    const float* __restrict__ corr, float* __restrict__ out,
    const float* __restrict__ mean_arr, float* __restrict__ out_det)
{
    const int pid = blockIdx.x;
    const int t = threadIdx.x;
    const float4* __restrict__ src = (const float4*)(corr + (size_t)pid * PLANE);
    float4* __restrict__ dst = (float4*)(out + (size_t)pid * PLANE);

    // issue the 3 streaming DRAM loads first (MLP=3), overlap with param math
    float4 c[3];
#pragma unroll
    for (int it = 0; it < 3; it++) c[it] = __ldcs(src + t + it * 192);

    // per-pixel params (redundant per thread; same-address broadcast, L2-hit)
    const int b = pid / PIXB;
    const float mu = g_stats[b * 2 + 0], istd = g_stats[b * 2 + 1];
    float c0 = (g_cvraw[pid * 2 + 0] - mu) * istd;
    float c1 = (g_cvraw[pid * 2 + 1] - mu) * istd;
    c0 = 5.f / (1.f + __expf(-c0)) + 0.05f;
    c1 = 5.f / (1.f + __expf(-c1)) + 0.05f;
    const float det = c0 * c1;
    if (t == 0) out_det[pid] = det;
    const float mx = __ldg(&mean_arr[pid * 2 + 0]);
    const float my = __ldg(&mean_arr[pid * 2 + 1]);
    const float ax = -0.5f / c0;
    const float ay = -0.5f / c1;
    const float s = rsqrtf(det) * (1.0f / 6.28f);

#pragma unroll
    for (int it = 0; it < 3; it++) {
        const int i = t + it * 192;          // float4 index in plane (0..575)
        const int h2 = i / 12;               // 12 float4s per 48-float row
        const float dy = (float)h2 - my;
        const bool iny = fabsf(dy) <= 6.0f;
        const float qy = ay * dy * dy;
        const float dx0 = (float)((i % 12) * 4) - mx;
        float4 v = c[it];
        {
            const float dx = dx0 + 0.f;
            if (iny && fabsf(dx) <= 6.0f)
                v.x = fmaf(v.x * s, __expf(fmaf(ax, dx * dx, qy)), v.x);
        }
        {
            const float dx = dx0 + 1.f;
            if (iny && fabsf(dx) <= 6.0f)
                v.y = fmaf(v.y * s, __expf(fmaf(ax, dx * dx, qy)), v.y);
        }
        {
            const float dx = dx0 + 2.f;
            if (iny && fabsf(dx) <= 6.0f)
                v.z = fmaf(v.z * s, __expf(fmaf(ax, dx * dx, qy)), v.z);
        }
        {
            const float dx = dx0 + 3.f;
            if (iny && fabsf(dx) <= 6.0f)
                v.w = fmaf(v.w * s, __expf(fmaf(ax, dx * dx, qy)), v.w);
        }
        __stcs(dst + i, v);
    }
}

// ======================================================================
extern "C" void kernel_launch(void* const* d_in, const int* in_sizes, int n_in,
                              void* d_out, int out_size)
{
    const float* x      = (const float*)d_in[0];
    const float* corr   = (const float*)d_in[1];
    const float* map_w  = (const float*)d_in[2];
    const float* map_b  = (const float*)d_in[3];
    const float* mean_w = (const float*)d_in[4];
    const float* mean_b = (const float*)d_in[5];
    const float* cov_w  = (const float*)d_in[6];
    const float* cov_b  = (const float*)d_in[7];

    float* out = (float*)d_out;
    // outputs concatenated flat: corr1 (b,h,w,h,w), mean (b,h,w,2), det (b,h*w)
    float* out_corr1 = out;
    float* out_mean  = out + (size_t)NPIX * PLANE;
    float* out_det   = out_mean + (size_t)NPIX * 2;

    k_stats<<<NBLK1, 256>>>(x, map_w, map_b, mean_w, mean_b, cov_w, cov_b, out_mean);
    k_apply<<<NPIX, 192>>>(corr, out_corr1, out_mean, out_det);
}